// round 8
// baseline (speedup 1.0000x reference)
#include <cuda_runtime.h>
#include <cuda_fp16.h>

// PassiveWaveDigitalMixer — fused 9-point periodic stencil + gated flows.
// B=4, C=128, H=W=256, O=16, M=32 (fixed shapes).
// R7: 2-row groups (grid = 512 -> 27.7 warps/SM of parallelism) + R5's
// packed-half2 gating + steer multipliers in shared (LDS.128) so the kernel
// fits in <=85 regs and 3 CTAs/SM become resident. All 8 row-vector loads
// front-batched per channel iteration (no staging — R6 lesson).

constexpr int B = 4, C = 128, H = 256, W = 256, O = 16, M = 32;
constexpr int HW = H * W;
constexpr float GAIN_CAP = 0.99f;
constexpr float EPS = 1e-4f;

__device__ __forceinline__ float softplus_eps(float p) {
    return fmaxf(p, 0.0f) + log1pf(expf(-fabsf(p))) + EPS;
}

__device__ __forceinline__ float4 add4(float4 a, float4 b) {
    return make_float4(a.x + b.x, a.y + b.y, a.z + b.z, a.w + b.w);
}

__device__ __forceinline__ __half2 u2h(unsigned u) {
    __half2 r;
    *reinterpret_cast<unsigned*>(&r) = u;
    return r;
}

__global__ __launch_bounds__(256, 3)
void pwdm_kernel(const float* __restrict__ x,
                 const float* __restrict__ steer,
                 const float* __restrict__ modulation,
                 const float* __restrict__ r_center,
                 const float* __restrict__ r_horizontal,
                 const float* __restrict__ r_vertical,
                 const float* __restrict__ r_diag,
                 const float* __restrict__ gain_h,
                 const float* __restrict__ gain_v,
                 const float* __restrict__ gain_d,
                 const float* __restrict__ steer_w,
                 const float* __restrict__ mod_w,
                 float* __restrict__ out)
{
    __shared__ float s_invh[C], s_invv[C], s_invd[C];
    __shared__ float s_gh[C],   s_gv[C],   s_gd[C];
    __shared__ __half s_t[2][3][W];   // pre-expanded (1 + 0.2*tanh(field))

    const int tx  = threadIdx.x;          // 0..31 lane (8 w-elems each)
    const int ty  = threadIdx.y;          // 0..7  channel sub-lane
    const int tid = ty * 32 + tx;
    const int h0  = blockIdx.x * 2;       // first of the row pair
    const int b   = blockIdx.y;

    // --- modulation deltas (broadcast loads, every thread) ---
    float d0 = 0.f, d1 = 0.f, d2 = 0.f;
    #pragma unroll
    for (int m = 0; m < M; m++) {
        float mv = modulation[b * M + m];
        d0 = fmaf(mv, mod_w[0 * M + m], d0);
        d1 = fmaf(mv, mod_w[1 * M + m], d1);
        d2 = fmaf(mv, mod_w[2 * M + m], d2);
    }
    d0 = tanhf(d0); d1 = tanhf(d1); d2 = tanhf(d2);

    // --- per-channel constants ---
    if (tid < C) {
        float spc = softplus_eps(r_center[tid]);
        s_invh[tid] = 1.0f / (spc + softplus_eps(r_horizontal[tid]));
        s_invv[tid] = 1.0f / (spc + softplus_eps(r_vertical[tid]));
        s_invd[tid] = 1.0f / (2.0f * (spc + softplus_eps(r_diag[tid])));
        s_gh[tid] = tanhf(gain_h[tid]) * (1.0f + 0.1f * d0);
        s_gv[tid] = tanhf(gain_v[tid]) * (1.0f + 0.1f * d1);
        s_gd[tid] = tanhf(gain_d[tid]) * (1.0f + 0.1f * d2);
    }

    // --- steer-field multipliers for the 2 rows; thread tid covers w=tid ---
    #pragma unroll
    for (int r = 0; r < 2; r++) {
        float a0 = 0.f, a1 = 0.f, a2 = 0.f;
        const float* sp = steer + ((size_t)b * O * H + (h0 + r)) * W + tid;
        #pragma unroll
        for (int o = 0; o < O; o++) {
            float v = sp[(size_t)o * HW];
            a0 = fmaf(v, steer_w[0 * O + o], a0);
            a1 = fmaf(v, steer_w[1 * O + o], a1);
            a2 = fmaf(v, steer_w[2 * O + o], a2);
        }
        s_t[r][0][tid] = __float2half(fmaf(0.2f, tanhf(a0), 1.0f));
        s_t[r][1][tid] = __float2half(fmaf(0.2f, tanhf(a1), 1.0f));
        s_t[r][2][tid] = __float2half(fmaf(0.2f, tanhf(a2), 1.0f));
    }
    __syncthreads();

    const int w0 = tx * 8;
    const int hm = (h0 - 1) & (H - 1);
    const int hp = (h0 + 2) & (H - 1);
    const size_t base = (size_t)b * C * HW + (size_t)ty * HW + w0;
    const float* pm = x + base + (size_t)hm * W;
    const float* p0 = x + base + (size_t)h0 * W;
    const float* pp = x + base + (size_t)hp * W;
    float*       o0 = out + base + (size_t)h0 * W;
    const size_t cstep = (size_t)8 * HW;

    const unsigned FULL = 0xffffffffu;
    const int laneL = (tx + 31) & 31;
    const int laneR = (tx + 1) & 31;
    const __half2 zero2 = __float2half2_rn(0.0f);
    const __half2 cap2  = __float2half2_rn(GAIN_CAP);

    float invh, invv, invd;
    __half2 gh2, gv2, gd2;

    // one output row: centers (cA,cB), vertical sums (sA,sB); steer mults
    // read from shared via 3x LDS.128.
    auto do_row = [&](float4 cA_, float4 cB_, float4 sA_, float4 sB_,
                      int r, float* op) {
        uint4 uH = *reinterpret_cast<const uint4*>(&s_t[r][0][w0]);
        uint4 uV = *reinterpret_cast<const uint4*>(&s_t[r][1][w0]);
        uint4 uD = *reinterpret_cast<const uint4*>(&s_t[r][2][w0]);
        unsigned mh[4] = {uH.x, uH.y, uH.z, uH.w};
        unsigned mv[4] = {uV.x, uV.y, uV.z, uV.w};
        unsigned md[4] = {uD.x, uD.y, uD.z, uD.w};

        float ce[10], se[10];
        ce[1] = cA_.x; ce[2] = cA_.y; ce[3] = cA_.z; ce[4] = cA_.w;
        ce[5] = cB_.x; ce[6] = cB_.y; ce[7] = cB_.z; ce[8] = cB_.w;
        se[1] = sA_.x; se[2] = sA_.y; se[3] = sA_.z; se[4] = sA_.w;
        se[5] = sB_.x; se[6] = sB_.y; se[7] = sB_.z; se[8] = sB_.w;
        ce[0] = __shfl_sync(FULL, ce[8], laneL);
        ce[9] = __shfl_sync(FULL, ce[1], laneR);
        se[0] = __shfl_sync(FULL, se[8], laneL);
        se[9] = __shfl_sync(FULL, se[1], laneR);

        float r8[8];
        #pragma unroll
        for (int j = 0; j < 4; j++) {
            __half2 gH = __hmin2(__hmax2(__hmul2(gh2, u2h(mh[j])), zero2), cap2);
            __half2 gV = __hmin2(__hmax2(__hmul2(gv2, u2h(mv[j])), zero2), cap2);
            __half2 gD = __hmin2(__hmax2(__hmul2(gd2, u2h(md[j])), zero2), cap2);
            float2 ghf = __half22float2(gH);
            float2 gvf = __half22float2(gV);
            float2 gdf = __half22float2(gD);
            #pragma unroll
            for (int k = 0; k < 2; k++) {
                const int i = 2 * j + k;
                float cv = ce[i + 1];
                float fh = (ce[i] + ce[i + 2] - 2.0f * cv) * invh;
                float fv = (se[i + 1]          - 2.0f * cv) * invv;
                float fd = (se[i] + se[i + 2]  - 4.0f * cv) * invd;
                float gh = k ? ghf.y : ghf.x;
                float gv = k ? gvf.y : gvf.x;
                float gd = k ? gdf.y : gdf.x;
                r8[i] = fmaf(gh, fh, fmaf(gv, fv, fmaf(gd, fd, cv)));
            }
        }
        *reinterpret_cast<float4*>(op)     = make_float4(r8[0], r8[1], r8[2], r8[3]);
        *reinterpret_cast<float4*>(op + 4) = make_float4(r8[4], r8[5], r8[6], r8[7]);
    };

    for (int c = ty; c < C; c += 8) {
        // front-batch ALL 8 row-vector loads (rows m, a, b, p) — max MLP
        float4 mA = *reinterpret_cast<const float4*>(pm);
        float4 mB = *reinterpret_cast<const float4*>(pm + 4);
        float4 aA = *reinterpret_cast<const float4*>(p0);
        float4 aB = *reinterpret_cast<const float4*>(p0 + 4);
        float4 bA = *reinterpret_cast<const float4*>(p0 + W);
        float4 bB = *reinterpret_cast<const float4*>(p0 + W + 4);
        float4 pA = *reinterpret_cast<const float4*>(pp);
        float4 pB = *reinterpret_cast<const float4*>(pp + 4);

        invh = s_invh[c]; invv = s_invv[c]; invd = s_invd[c];
        gh2 = __float2half2_rn(s_gh[c]);
        gv2 = __float2half2_rn(s_gv[c]);
        gd2 = __float2half2_rn(s_gd[c]);

        // row h0: vsum = m + b
        do_row(aA, aB, add4(mA, bA), add4(mB, bB), 0, o0);
        // row h1: vsum = a + p
        do_row(bA, bB, add4(aA, pA), add4(aB, pB), 1, o0 + W);

        pm += cstep; p0 += cstep; pp += cstep; o0 += cstep;
    }
}

extern "C" void kernel_launch(void* const* d_in, const int* in_sizes, int n_in,
                              void* d_out, int out_size)
{
    const float* x            = (const float*)d_in[0];
    const float* steer        = (const float*)d_in[1];
    const float* modulation   = (const float*)d_in[2];
    const float* r_center     = (const float*)d_in[3];
    const float* r_horizontal = (const float*)d_in[4];
    const float* r_vertical   = (const float*)d_in[5];
    const float* r_diag       = (const float*)d_in[6];
    const float* gain_h       = (const float*)d_in[7];
    const float* gain_v       = (const float*)d_in[8];
    const float* gain_d       = (const float*)d_in[9];
    const float* steer_w      = (const float*)d_in[10];
    const float* mod_w        = (const float*)d_in[11];
    float* out = (float*)d_out;

    dim3 block(32, 8, 1);       // one warp per full W row-pair, 8 channel lanes
    dim3 grid(H / 2, B, 1);     // 512 blocks -> 3 CTAs/SM residency possible
    pwdm_kernel<<<grid, block>>>(x, steer, modulation,
                                 r_center, r_horizontal, r_vertical, r_diag,
                                 gain_h, gain_v, gain_d,
                                 steer_w, mod_w, out);
}

// round 9
// speedup vs baseline: 1.1875x; 1.1875x over previous
#include <cuda_runtime.h>
#include <cuda_fp16.h>

// PassiveWaveDigitalMixer — fused 9-point periodic stencil + gated flows.
// B=4, C=128, H=W=256, O=16, M=32 (fixed shapes).
// R8 = R5 structure (warp = full W row x 4 consecutive h rows per channel
// iteration, horizontal halos via warp shuffle, steer multipliers as half2 in
// registers, packed-half2 gating) + flow/accumulate math in packed f32x2
// (FFMA2/FADD2/FMUL2 via PTX) — half the fp32 issue slots, bit-identical math.

constexpr int B = 4, C = 128, H = 256, W = 256, O = 16, M = 32;
constexpr int HW = H * W;
constexpr float GAIN_CAP = 0.99f;
constexpr float EPS = 1e-4f;

using ull = unsigned long long;

__device__ __forceinline__ float softplus_eps(float p) {
    return fmaxf(p, 0.0f) + log1pf(expf(-fabsf(p))) + EPS;
}

// ---- packed f32x2 helpers ----
__device__ __forceinline__ ull pk2(float lo, float hi) {
    ull r;
    asm("mov.b64 %0, {%1, %2};" : "=l"(r) : "f"(lo), "f"(hi));
    return r;
}
__device__ __forceinline__ float lo2(ull v) {
    float a, b;
    asm("mov.b64 {%0, %1}, %2;" : "=f"(a), "=f"(b) : "l"(v));
    return a;
}
__device__ __forceinline__ float hi2(ull v) {
    float a, b;
    asm("mov.b64 {%0, %1}, %2;" : "=f"(a), "=f"(b) : "l"(v));
    return b;
}
__device__ __forceinline__ ull bc2(float s) { return pk2(s, s); }
__device__ __forceinline__ ull fma2(ull a, ull b, ull c) {
    ull d;
    asm("fma.rn.f32x2 %0, %1, %2, %3;" : "=l"(d) : "l"(a), "l"(b), "l"(c));
    return d;
}
__device__ __forceinline__ ull add2(ull a, ull b) {
    ull d;
    asm("add.rn.f32x2 %0, %1, %2;" : "=l"(d) : "l"(a), "l"(b));
    return d;
}
__device__ __forceinline__ ull mul2(ull a, ull b) {
    ull d;
    asm("mul.rn.f32x2 %0, %1, %2;" : "=l"(d) : "l"(a), "l"(b));
    return d;
}

__global__ __launch_bounds__(256, 2)
void pwdm_kernel(const float* __restrict__ x,
                 const float* __restrict__ steer,
                 const float* __restrict__ modulation,
                 const float* __restrict__ r_center,
                 const float* __restrict__ r_horizontal,
                 const float* __restrict__ r_vertical,
                 const float* __restrict__ r_diag,
                 const float* __restrict__ gain_h,
                 const float* __restrict__ gain_v,
                 const float* __restrict__ gain_d,
                 const float* __restrict__ steer_w,
                 const float* __restrict__ mod_w,
                 float* __restrict__ out)
{
    __shared__ float s_invh[C], s_invv[C], s_invd[C];
    __shared__ float s_gh[C],   s_gv[C],   s_gd[C];
    __shared__ __half s_t[4][3][W];   // pre-expanded (1 + 0.2*tanh(field))

    const int tx  = threadIdx.x;          // 0..31 lane (8 w-elems each)
    const int ty  = threadIdx.y;          // 0..7  channel sub-lane
    const int tid = ty * 32 + tx;
    const int h0  = blockIdx.x * 4;       // first of the 4-row group
    const int b   = blockIdx.y;

    // --- modulation deltas (broadcast loads, every thread) ---
    float d0 = 0.f, d1 = 0.f, d2 = 0.f;
    #pragma unroll
    for (int m = 0; m < M; m++) {
        float mv = modulation[b * M + m];
        d0 = fmaf(mv, mod_w[0 * M + m], d0);
        d1 = fmaf(mv, mod_w[1 * M + m], d1);
        d2 = fmaf(mv, mod_w[2 * M + m], d2);
    }
    d0 = tanhf(d0); d1 = tanhf(d1); d2 = tanhf(d2);

    // --- per-channel constants ---
    if (tid < C) {
        float spc = softplus_eps(r_center[tid]);
        s_invh[tid] = 1.0f / (spc + softplus_eps(r_horizontal[tid]));
        s_invv[tid] = 1.0f / (spc + softplus_eps(r_vertical[tid]));
        s_invd[tid] = 1.0f / (2.0f * (spc + softplus_eps(r_diag[tid])));
        s_gh[tid] = tanhf(gain_h[tid]) * (1.0f + 0.1f * d0);
        s_gv[tid] = tanhf(gain_v[tid]) * (1.0f + 0.1f * d1);
        s_gd[tid] = tanhf(gain_d[tid]) * (1.0f + 0.1f * d2);
    }

    // --- steer-field multipliers for 4 rows; thread tid covers w = tid ---
    #pragma unroll
    for (int r = 0; r < 4; r++) {
        float a0 = 0.f, a1 = 0.f, a2 = 0.f;
        const float* sp = steer + ((size_t)b * O * H + (h0 + r)) * W + tid;
        #pragma unroll
        for (int o = 0; o < O; o++) {
            float v = sp[(size_t)o * HW];
            a0 = fmaf(v, steer_w[0 * O + o], a0);
            a1 = fmaf(v, steer_w[1 * O + o], a1);
            a2 = fmaf(v, steer_w[2 * O + o], a2);
        }
        s_t[r][0][tid] = __float2half(fmaf(0.2f, tanhf(a0), 1.0f));
        s_t[r][1][tid] = __float2half(fmaf(0.2f, tanhf(a1), 1.0f));
        s_t[r][2][tid] = __float2half(fmaf(0.2f, tanhf(a2), 1.0f));
    }
    __syncthreads();

    // --- hoist this lane's multipliers: 4 rows x 3 dirs x 4 half2 regs ---
    const int w0 = tx * 8;
    __half2 st[4][3][4];
    #pragma unroll
    for (int r = 0; r < 4; r++)
        #pragma unroll
        for (int dir = 0; dir < 3; dir++)
            #pragma unroll
            for (int j = 0; j < 4; j++)
                st[r][dir][j] =
                    *reinterpret_cast<const __half2*>(&s_t[r][dir][w0 + 2 * j]);

    const int hm = (h0 - 1) & (H - 1);
    const int hp = (h0 + 4) & (H - 1);
    const size_t base = (size_t)b * C * HW + (size_t)ty * HW + w0;
    const float* pm = x + base + (size_t)hm * W;
    const float* p0 = x + base + (size_t)h0 * W;
    const float* pp = x + base + (size_t)hp * W;
    float*       o0 = out + base + (size_t)h0 * W;
    const size_t cstep = (size_t)8 * HW;

    const unsigned FULL = 0xffffffffu;
    const int laneL = (tx + 31) & 31;
    const int laneR = (tx + 1) & 31;
    const __half2 zero2 = __float2half2_rn(0.0f);
    const __half2 cap2  = __float2half2_rn(GAIN_CAP);
    const ull M2 = bc2(-2.0f);
    const ull M4 = bc2(-4.0f);

    ull invh2, invv2, invd2;
    __half2 gh2, gv2, gd2;

    // one output row: centers cP[4] (aligned f32x2 packs), vertical-sum packs
    // sP[4]; r selects the steer-multiplier row; op is the output address.
    auto do_row = [&](const ull (&cP)[4], const ull (&sP)[4], int r, float* op) {
        // periodic horizontal halos via warp shuffle
        float ceL = __shfl_sync(FULL, hi2(cP[3]), laneL);
        float ceR = __shfl_sync(FULL, lo2(cP[0]), laneR);
        float seL = __shfl_sync(FULL, hi2(sP[3]), laneL);
        float seR = __shfl_sync(FULL, lo2(sP[0]), laneR);

        // left-shifted (odd-aligned) packs: B_j = (elem[2j-1], elem[2j])
        ull cB[5], sB[5];
        cB[0] = pk2(ceL, lo2(cP[0]));
        sB[0] = pk2(seL, lo2(sP[0]));
        #pragma unroll
        for (int j = 1; j < 4; j++) {
            cB[j] = pk2(hi2(cP[j - 1]), lo2(cP[j]));
            sB[j] = pk2(hi2(sP[j - 1]), lo2(sP[j]));
        }
        cB[4] = pk2(hi2(cP[3]), ceR);
        sB[4] = pk2(hi2(sP[3]), seR);

        ull o[4];
        #pragma unroll
        for (int j = 0; j < 4; j++) {
            // packed half2 gating: gain = clamp(g_c * mult, 0, cap)
            __half2 gH = __hmin2(__hmax2(__hmul2(gh2, st[r][0][j]), zero2), cap2);
            __half2 gV = __hmin2(__hmax2(__hmul2(gv2, st[r][1][j]), zero2), cap2);
            __half2 gD = __hmin2(__hmax2(__hmul2(gd2, st[r][2][j]), zero2), cap2);
            float2 ghf = __half22float2(gH);
            float2 gvf = __half22float2(gV);
            float2 gdf = __half22float2(gD);
            ull ghp = pk2(ghf.x, ghf.y);
            ull gvp = pk2(gvf.x, gvf.y);
            ull gdp = pk2(gdf.x, gdf.y);

            // flows (packed f32x2, bit-identical per lane to scalar fp32)
            ull nh = fma2(cP[j], M2, add2(cB[j], cB[j + 1]));
            ull nv = fma2(cP[j], M2, sP[j]);
            ull nd = fma2(cP[j], M4, add2(sB[j], sB[j + 1]));
            ull fh = mul2(nh, invh2);
            ull fv = mul2(nv, invv2);
            ull fd = mul2(nd, invd2);

            ull acc = fma2(gdp, fd, cP[j]);
            acc     = fma2(gvp, fv, acc);
            acc     = fma2(ghp, fh, acc);
            o[j] = acc;
        }
        ulonglong2 ov0; ov0.x = o[0]; ov0.y = o[1];
        ulonglong2 ov1; ov1.x = o[2]; ov1.y = o[3];
        *reinterpret_cast<ulonglong2*>(op)     = ov0;
        *reinterpret_cast<ulonglong2*>(op + 4) = ov1;
    };

    for (int c = ty; c < C; c += 8) {
        // front-batch all 12 row-vector loads (rows m, a, b, c, d, p) — max MLP
        ulonglong2 mv0 = *reinterpret_cast<const ulonglong2*>(pm);
        ulonglong2 mv1 = *reinterpret_cast<const ulonglong2*>(pm + 4);
        ulonglong2 av0 = *reinterpret_cast<const ulonglong2*>(p0);
        ulonglong2 av1 = *reinterpret_cast<const ulonglong2*>(p0 + 4);
        ulonglong2 bv0 = *reinterpret_cast<const ulonglong2*>(p0 + W);
        ulonglong2 bv1 = *reinterpret_cast<const ulonglong2*>(p0 + W + 4);
        ulonglong2 cv0 = *reinterpret_cast<const ulonglong2*>(p0 + 2 * W);
        ulonglong2 cv1 = *reinterpret_cast<const ulonglong2*>(p0 + 2 * W + 4);
        ulonglong2 dv0 = *reinterpret_cast<const ulonglong2*>(p0 + 3 * W);
        ulonglong2 dv1 = *reinterpret_cast<const ulonglong2*>(p0 + 3 * W + 4);
        ulonglong2 pv0 = *reinterpret_cast<const ulonglong2*>(pp);
        ulonglong2 pv1 = *reinterpret_cast<const ulonglong2*>(pp + 4);

        ull mP[4]  = {mv0.x, mv0.y, mv1.x, mv1.y};
        ull aP[4]  = {av0.x, av0.y, av1.x, av1.y};
        ull bP[4]  = {bv0.x, bv0.y, bv1.x, bv1.y};
        ull cPk[4] = {cv0.x, cv0.y, cv1.x, cv1.y};
        ull dP[4]  = {dv0.x, dv0.y, dv1.x, dv1.y};
        ull pP[4]  = {pv0.x, pv0.y, pv1.x, pv1.y};

        invh2 = bc2(s_invh[c]); invv2 = bc2(s_invv[c]); invd2 = bc2(s_invd[c]);
        gh2 = __float2half2_rn(s_gh[c]);
        gv2 = __float2half2_rn(s_gv[c]);
        gd2 = __float2half2_rn(s_gd[c]);

        ull sP[4];

        // row h0: vsum = m + b
        #pragma unroll
        for (int j = 0; j < 4; j++) sP[j] = add2(mP[j], bP[j]);
        do_row(aP, sP, 0, o0);
        // row h1: vsum = a + c
        #pragma unroll
        for (int j = 0; j < 4; j++) sP[j] = add2(aP[j], cPk[j]);
        do_row(bP, sP, 1, o0 + W);
        // row h2: vsum = b + d
        #pragma unroll
        for (int j = 0; j < 4; j++) sP[j] = add2(bP[j], dP[j]);
        do_row(cPk, sP, 2, o0 + 2 * W);
        // row h3: vsum = c + p
        #pragma unroll
        for (int j = 0; j < 4; j++) sP[j] = add2(cPk[j], pP[j]);
        do_row(dP, sP, 3, o0 + 3 * W);

        pm += cstep; p0 += cstep; pp += cstep; o0 += cstep;
    }
}

extern "C" void kernel_launch(void* const* d_in, const int* in_sizes, int n_in,
                              void* d_out, int out_size)
{
    const float* x            = (const float*)d_in[0];
    const float* steer        = (const float*)d_in[1];
    const float* modulation   = (const float*)d_in[2];
    const float* r_center     = (const float*)d_in[3];
    const float* r_horizontal = (const float*)d_in[4];
    const float* r_vertical   = (const float*)d_in[5];
    const float* r_diag       = (const float*)d_in[6];
    const float* gain_h       = (const float*)d_in[7];
    const float* gain_v       = (const float*)d_in[8];
    const float* gain_d       = (const float*)d_in[9];
    const float* steer_w      = (const float*)d_in[10];
    const float* mod_w        = (const float*)d_in[11];
    float* out = (float*)d_out;

    dim3 block(32, 8, 1);       // one warp per full W row-quad, 8 channel lanes
    dim3 grid(H / 4, B, 1);     // one block per (4-row group, b)
    pwdm_kernel<<<grid, block>>>(x, steer, modulation,
                                 r_center, r_horizontal, r_vertical, r_diag,
                                 gain_h, gain_v, gain_d,
                                 steer_w, mod_w, out);
}